// round 5
// baseline (speedup 1.0000x reference)
#include <cuda_runtime.h>
#include <math.h>

#define Bc 2
#define Hc 1080
#define Wc 1920
#define Kc 2048
#define Pc 256
#define NROWS 64
#define PITCH 66     // even => 8B-aligned rows; (66 mod 32)=2 keeps phases conflict-free
#define SEGW 9

__global__ __launch_bounds__(512, 3)
void brief_desc_kernel(const float* __restrict__ img,
                       const float* __restrict__ kp,
                       const float* __restrict__ ori,
                       const float* __restrict__ oy1v,
                       const float* __restrict__ ox1v,
                       const float* __restrict__ oy2v,
                       const float* __restrict__ ox2v,
                       const float* __restrict__ thr,
                       const int*   __restrict__ radii,
                       float* __restrict__ out)
{
    __shared__ float S[NROWS * PITCH];        // 16.9 KB : row-prefix, then SAT
    __shared__ float segtot[NROWS * SEGW];    // 2.25 KB : reused row->col phase
    __shared__ float pd[2 * Pc];
    __shared__ float red[8];

    const int blk = blockIdx.x;               // b*K + k
    const int b   = blk / Kc;
    const int tid = threadIdx.x;

    // --- keypoint, validity, orientation (broadcast loads) ---
    const float kpy = kp[blk * 2 + 0];
    const float kpx = kp[blk * 2 + 1];
    const float valid = (kpy >= 0.0f) ? 1.0f : 0.0f;
    const float y = fminf(fmaxf(kpy, 0.0f), (float)(Hc - 1));
    const float x = fminf(fmaxf(kpx, 0.0f), (float)(Wc - 1));
    const int iy = (int)rintf(y);              // round-half-even == jnp.round
    const int ix = (int)rintf(x);

    const float* imb = img + (size_t)b * Hc * Wc;
    const float theta = ori[(size_t)b * Hc * Wc + (size_t)iy * Wc + ix];
    float st, ct;
    sincosf(theta, &st, &ct);

    const int oy0 = iy - 31;
    const int ox0 = ix - 31;

    // ============ Phase A: load + row prefix, entirely in registers ============
    {
        const int r = tid >> 3;                // row 0..63
        const int q = tid & 7;                 // 8-col segment
        const int gy = oy0 + r;
        const int gxb = ox0 + q * 8;
        const bool rowok = (gy >= 0) & (gy < Hc);
        const float* rowp = imb + (size_t)(rowok ? gy : 0) * Wc;

        float v[8];
        float s = 0.0f;
        #pragma unroll
        for (int j = 0; j < 8; j++) {
            const int gx = gxb + j;
            float e = 0.0f;
            if (rowok && gx >= 0 && gx < Wc) e = rowp[gx];
            s += e;
            v[j] = s;
        }
        segtot[r * SEGW + q] = s;
        __syncthreads();

        float off = 0.0f;
        #pragma unroll
        for (int qq = 0; qq < 7; qq++)
            if (qq < q) off += segtot[r * SEGW + qq];

        const int base = r * PITCH + q * 8;
        #pragma unroll
        for (int j = 0; j < 8; j += 2) {       // STS.64, conflict-free per phase
            float2 w2 = make_float2(v[j] + off, v[j + 1] + off);
            *reinterpret_cast<float2*>(&S[base + j]) = w2;
        }
    }
    __syncthreads();

    // ============ Phase B: segmented column prefix ============
    {
        const int c = tid & 63;                // column
        const int m = tid >> 6;                // 8-row segment, 0..7
        const int base = (m * 8) * PITCH + c;

        float w[8];
        float s = 0.0f;
        #pragma unroll
        for (int i = 0; i < 8; i++) { s += S[base + i * PITCH]; w[i] = s; }
        segtot[c * SEGW + m] = s;
        __syncthreads();

        float off = 0.0f;
        #pragma unroll
        for (int mm = 0; mm < 7; mm++)
            if (mm < m) off += segtot[c * SEGW + mm];

        #pragma unroll
        for (int i = 0; i < 8; i++) S[base + i * PITCH] = w[i] + off;
    }
    __syncthreads();

    // ============ Phase C: sampling (half block per test point) ============
    {
        const int p    = tid & 255;
        const int half = tid >> 8;             // 0 -> point1, 1 -> point2
        const float oy = half ? oy2v[p] : oy1v[p];
        const float ox = half ? ox2v[p] : ox1v[p];
        const int   r  = radii[p];
        const float dn = (float)(2 * r + 1);
        const float invden = 1.0f / (dn * dn);

        const float py = y + (ox * st + oy * ct);
        const float px = x + (ox * ct - oy * st);

        // reference order: round first, then clip
        const float jyf = fminf(fmaxf(rintf(py), 0.0f), (float)(Hc - 1));
        const float jxf = fminf(fmaxf(rintf(px), 0.0f), (float)(Wc - 1));
        const int ly = (int)jyf - oy0;         // in [8,54]
        const int lx = (int)jxf - ox0;
        const int y1 = ly - r - 1, y2 = ly + r;
        const int x1 = lx - r - 1, x2 = lx + r;
        const float s = S[y2 * PITCH + x2] - S[y1 * PITCH + x2]
                      - S[y2 * PITCH + x1] + S[y1 * PITCH + x1];
        pd[half * Pc + p] = s * invden;
    }
    __syncthreads();

    // ============ Phase D: combine, L2-normalize, write ============
    float d = 0.0f;
    if (tid < Pc)
        d = pd[tid] - pd[Pc + tid] - thr[tid];

    float sq = d * d;
    #pragma unroll
    for (int off = 16; off; off >>= 1)
        sq += __shfl_xor_sync(0xffffffffu, sq, off);
    if (tid < Pc && (tid & 31) == 0) red[tid >> 5] = sq;
    __syncthreads();

    if (tid < Pc) {
        const float tot = red[0] + red[1] + red[2] + red[3]
                        + red[4] + red[5] + red[6] + red[7];
        const float norm  = sqrtf(tot);
        const float scale = valid / fmaxf(norm, 1e-12f);
        out[(size_t)blk * Pc + tid] = d * scale;
    }
}

extern "C" void kernel_launch(void* const* d_in, const int* in_sizes, int n_in,
                              void* d_out, int out_size)
{
    const float* img  = (const float*)d_in[0];  // image (B,1,H,W)
    const float* kp   = (const float*)d_in[1];  // keypoints (B,K,2)
    const float* ori  = (const float*)d_in[2];  // orientation (B,1,H,W)
    const float* oy1  = (const float*)d_in[3];
    const float* ox1  = (const float*)d_in[4];
    const float* oy2  = (const float*)d_in[5];
    const float* ox2  = (const float*)d_in[6];
    const float* thr  = (const float*)d_in[7];
    const int*   rad  = (const int*)d_in[8];
    float* out = (float*)d_out;

    brief_desc_kernel<<<Bc * Kc, 512>>>(img, kp, ori, oy1, ox1, oy2, ox2, thr, rad, out);
}

// round 6
// speedup vs baseline: 1.7449x; 1.7449x over previous
#include <cuda_runtime.h>
#include <math.h>

#define Bc 2
#define Hc 1080
#define Wc 1920
#define Kc 2048
#define Pc 256

// SAT stored swizzled: element (r,c) lives at  r*64 + ((c>>2 ^ (r&7))<<2) + (c&3)
__device__ __forceinline__ int swz(int r, int c) {
    return (r << 6) + ((((c >> 2) ^ (r & 7)) << 2) | (c & 3));
}

__global__ __launch_bounds__(256)
void brief_desc_kernel(const float* __restrict__ img,
                       const float* __restrict__ kp,
                       const float* __restrict__ ori,
                       const float* __restrict__ oy1v,
                       const float* __restrict__ ox1v,
                       const float* __restrict__ oy2v,
                       const float* __restrict__ ox2v,
                       const float* __restrict__ thr,
                       const int*   __restrict__ radii,
                       float* __restrict__ out)
{
    __shared__ float S[64 * 64];     // 16 KB, swizzled SAT
    __shared__ float red[8];

    const int blk = blockIdx.x;      // b*K + k
    const int b   = blk / Kc;
    const int tid = threadIdx.x;

    // --- pattern constants: issue these loads early (independent of patch) ---
    const float o_y1 = oy1v[tid];
    const float o_x1 = ox1v[tid];
    const float o_y2 = oy2v[tid];
    const float o_x2 = ox2v[tid];
    const float th   = thr[tid];
    const int   rad  = radii[tid];

    // --- keypoint, validity, orientation (broadcast loads) ---
    const float kpy = kp[blk * 2 + 0];
    const float kpx = kp[blk * 2 + 1];
    const float valid = (kpy >= 0.0f) ? 1.0f : 0.0f;
    const float y = fminf(fmaxf(kpy, 0.0f), (float)(Hc - 1));
    const float x = fminf(fmaxf(kpx, 0.0f), (float)(Wc - 1));
    const int iy = (int)rintf(y);    // round-half-even == jnp.round
    const int ix = (int)rintf(x);

    const float* imb = img + (size_t)b * Hc * Wc;
    const float theta = ori[(size_t)b * Hc * Wc + (size_t)iy * Wc + ix];
    float st, ct;
    sincosf(theta, &st, &ct);

    // patch origin; x-origin floored to a multiple of 4 for aligned float4 LDG.
    // Sample corners then fall in rows [1,60], cols [1,63] of the 64x64 patch.
    const int oy0 = iy - 31;
    const int ox0 = (ix - 31) & ~3;

    // ===== Phase A: fused load + row prefix (coalesced float4 + shfl scan) =====
    {
        const int lane16 = tid & 15;          // chunk index within row
        const int grp    = tid >> 4;          // 16 row-groups; warp = 2 rows
        const int k8     = grp & 7;           // (row & 7) is pass-invariant
        const int cs4    = (lane16 ^ k8) << 2;
        const int gxc    = ox0 + (lane16 << 2);
        const bool xok   = (gxc >= 0) & (gxc <= Wc - 4);  // chunks never straddle

        #pragma unroll
        for (int p = 0; p < 4; p++) {
            const int r  = (p << 4) + grp;
            const int gy = oy0 + r;
            float4 e = make_float4(0.f, 0.f, 0.f, 0.f);
            if (xok && gy >= 0 && gy < Hc)
                e = *reinterpret_cast<const float4*>(imb + (size_t)gy * Wc + gxc);

            float v0 = e.x;
            float v1 = v0 + e.y;
            float v2 = v1 + e.z;
            float v3 = v2 + e.w;

            float t = v3;                     // inclusive scan of chunk totals
            #pragma unroll
            for (int d = 1; d < 16; d <<= 1) {
                const float n = __shfl_up_sync(0xffffffffu, t, d, 16);
                if (lane16 >= d) t += n;
            }
            const float off = t - v3;         // exclusive prefix for this chunk

            *reinterpret_cast<float4*>(&S[(r << 6) + cs4]) =
                make_float4(v0 + off, v1 + off, v2 + off, v3 + off);
        }
    }
    __syncthreads();

    // ===== Phase B: column prefix (serial, 64 threads, conflict-free) =====
    if (tid < 64) {
        const int cx = tid >> 2;
        const int cl = tid & 3;
        float s = 0.0f;
        #pragma unroll
        for (int r = 0; r < 64; r++) {
            const int a = (r << 6) + (((cx ^ (r & 7)) << 2) | cl);
            s += S[a];
            S[a] = s;
        }
    }
    __syncthreads();

    // ===== Phase C: sampling — both test points per thread =====
    const float dn = (float)(2 * rad + 1);
    const float invden = 1.0f / (dn * dn);

    const float p1y = y + (o_x1 * st + o_y1 * ct);
    const float p1x = x + (o_x1 * ct - o_y1 * st);
    const float p2y = y + (o_x2 * st + o_y2 * ct);
    const float p2x = x + (o_x2 * ct - o_y2 * st);

    auto boxavg = [&](float py, float px) -> float {
        // reference order: round first, then clip
        const float jyf = fminf(fmaxf(rintf(py), 0.0f), (float)(Hc - 1));
        const float jxf = fminf(fmaxf(rintf(px), 0.0f), (float)(Wc - 1));
        const int ly = (int)jyf - oy0;        // in [8,54]
        const int lx = (int)jxf - ox0;        // in [8,57]
        const int y1 = ly - rad - 1, y2 = ly + rad;
        const int x1 = lx - rad - 1, x2 = lx + rad;
        const float s = S[swz(y2, x2)] - S[swz(y1, x2)]
                      - S[swz(y2, x1)] + S[swz(y1, x1)];
        return s * invden;
    };

    const float d = boxavg(p1y, p1x) - boxavg(p2y, p2x) - th;

    // ===== Phase D: L2 normalize + write =====
    float sq = d * d;
    #pragma unroll
    for (int off = 16; off; off >>= 1)
        sq += __shfl_xor_sync(0xffffffffu, sq, off);
    if ((tid & 31) == 0) red[tid >> 5] = sq;
    __syncthreads();
    const float tot = red[0] + red[1] + red[2] + red[3]
                    + red[4] + red[5] + red[6] + red[7];
    const float norm  = sqrtf(tot);
    const float scale = valid / fmaxf(norm, 1e-12f);

    out[(size_t)blk * Pc + tid] = d * scale;
}

extern "C" void kernel_launch(void* const* d_in, const int* in_sizes, int n_in,
                              void* d_out, int out_size)
{
    const float* img  = (const float*)d_in[0];  // image (B,1,H,W)
    const float* kp   = (const float*)d_in[1];  // keypoints (B,K,2)
    const float* ori  = (const float*)d_in[2];  // orientation (B,1,H,W)
    const float* oy1  = (const float*)d_in[3];
    const float* ox1  = (const float*)d_in[4];
    const float* oy2  = (const float*)d_in[5];
    const float* ox2  = (const float*)d_in[6];
    const float* thr  = (const float*)d_in[7];
    const int*   rad  = (const int*)d_in[8];
    float* out = (float*)d_out;

    brief_desc_kernel<<<Bc * Kc, Pc>>>(img, kp, ori, oy1, ox1, oy2, ox2, thr, rad, out);
}